// round 10
// baseline (speedup 1.0000x reference)
#include <cuda_runtime.h>
#include <cuda_bf16.h>
#include <cstdint>

// ---------------------------------------------------------------------------
// Problem: B=128, F=1024, W=32, H=64.  softmax over a size-1 axis == 1, so the
// attention branch is dead; model = plain LSTM, output = CELL state per step.
//   G[m][n] = sum_k x[b][k][t] * Wx[k][n] + b_lstm[n],  m = b*32 + t
// GEMM: bf16 mma.sync, 3-pass hi/lo compensation (rel_err ~1.6e-5 proven).
// ---------------------------------------------------------------------------
#define B_   128
#define F_   1024
#define W_   32
#define H_   64
#define G4   256
#define PADK 40                  // smem row stride in bf16 (80B): conflict-free

__device__ float          g_G [B_ * W_ * G4];    // gate preactivations, 4 MB
__device__ __nv_bfloat16  g_xh[B_ * W_ * F_];    // x^T hi  [m][k], 8 MB
__device__ __nv_bfloat16  g_xl[B_ * W_ * F_];    // x^T lo
__device__ __nv_bfloat16  g_wh[G4 * F_];         // Wx^T hi [n][k], 512 KB
__device__ __nv_bfloat16  g_wl[G4 * F_];         // Wx^T lo

// ---- helpers ---------------------------------------------------------------
__device__ __forceinline__ uint32_t smaddr(const void* p) {
    return (uint32_t)__cvta_generic_to_shared(p);
}
__device__ __forceinline__ void split2(float a, float b, uint32_t& hi, uint32_t& lo) {
    uint32_t ua = __float_as_uint(a), ub = __float_as_uint(b);
    hi = (ua >> 16) | (ub & 0xFFFF0000u);                   // truncated bf16 pair
    float la = a - __uint_as_float(ua & 0xFFFF0000u);
    float lb = b - __uint_as_float(ub & 0xFFFF0000u);
    __nv_bfloat162 p = __floats2bfloat162_rn(la, lb);
    lo = *reinterpret_cast<uint32_t*>(&p);
}
__device__ __forceinline__ void mma_bf16(float* c,
                                         const uint32_t* a, uint32_t b0, uint32_t b1) {
    asm volatile(
        "mma.sync.aligned.m16n8k16.row.col.f32.bf16.bf16.f32 "
        "{%0,%1,%2,%3}, {%4,%5,%6,%7}, {%8,%9}, {%0,%1,%2,%3};\n"
        : "+f"(c[0]), "+f"(c[1]), "+f"(c[2]), "+f"(c[3])
        : "r"(a[0]), "r"(a[1]), "r"(a[2]), "r"(a[3]), "r"(b0), "r"(b1));
}
__device__ __forceinline__ void ldsm4(uint32_t* r, uint32_t addr) {
    asm volatile("ldmatrix.sync.aligned.m8n8.x4.shared.b16 {%0,%1,%2,%3}, [%4];"
                 : "=r"(r[0]), "=r"(r[1]), "=r"(r[2]), "=r"(r[3]) : "r"(addr));
}

// ---------------------------------------------------------------------------
// Kernel 0 (fused): transpose + hi/lo split of x and Wx.
//   blocks [0, 1024):  x [B][F][W] -> g_xh/g_xl [m=b*32+t][k=f]
//   blocks [1024, 1088): Wx [K][N] -> g_wh/g_wl [n][k]
// ---------------------------------------------------------------------------
__global__ __launch_bounds__(256) void split_xw(const float* __restrict__ x,
                                                const float* __restrict__ Wx) {
    __shared__ float tile[128 * 33 > 64 * 65 ? 128 * 33 : 64 * 65];
    const int tid = threadIdx.x;
    const int bid = blockIdx.x;

    if (bid < 1024) {
        // ----- x path: tile = [128 f][33 pad] of x[b][f0+f][t] -----
        const int b  = bid >> 3;
        const int f0 = (bid & 7) * 128;
#pragma unroll
        for (int i = 0; i < 4; i++) {
            int idx = i * 256 + tid;
            int f = idx >> 3, tq = idx & 7;
            float4 v = *reinterpret_cast<const float4*>(
                x + ((size_t)b * F_ + f0 + f) * W_ + tq * 4);
            tile[f * 33 + tq * 4 + 0] = v.x; tile[f * 33 + tq * 4 + 1] = v.y;
            tile[f * 33 + tq * 4 + 2] = v.z; tile[f * 33 + tq * 4 + 3] = v.w;
        }
        __syncthreads();
        const int t  = tid >> 3;
        const int fo = (tid & 7) * 16;
        uint32_t hi[8], lo[8];
#pragma unroll
        for (int p = 0; p < 8; p++)
            split2(tile[(fo + 2 * p) * 33 + t], tile[(fo + 2 * p + 1) * 33 + t],
                   hi[p], lo[p]);
        size_t dst = ((size_t)b * W_ + t) * F_ + f0 + fo;
        *reinterpret_cast<uint4*>(g_xh + dst)     = make_uint4(hi[0], hi[1], hi[2], hi[3]);
        *reinterpret_cast<uint4*>(g_xh + dst + 8) = make_uint4(hi[4], hi[5], hi[6], hi[7]);
        *reinterpret_cast<uint4*>(g_xl + dst)     = make_uint4(lo[0], lo[1], lo[2], lo[3]);
        *reinterpret_cast<uint4*>(g_xl + dst + 8) = make_uint4(lo[4], lo[5], lo[6], lo[7]);
    } else {
        // ----- Wx path: tile = [64 k][65 pad] of Wx[k0+k][n0+n] -----
        const int id = bid - 1024;
        const int k0 = (id & 15) * 64;
        const int n0 = (id >> 4) * 64;
#pragma unroll
        for (int i = 0; i < 4; i++) {
            int idx = i * 256 + tid;
            int k = idx >> 4, nq = idx & 15;
            float4 v = *reinterpret_cast<const float4*>(
                Wx + (size_t)(k0 + k) * G4 + n0 + nq * 4);
            tile[k * 65 + nq * 4 + 0] = v.x; tile[k * 65 + nq * 4 + 1] = v.y;
            tile[k * 65 + nq * 4 + 2] = v.z; tile[k * 65 + nq * 4 + 3] = v.w;
        }
        __syncthreads();
        const int n  = tid >> 2;
        const int ko = (tid & 3) * 16;
        uint32_t hi[8], lo[8];
#pragma unroll
        for (int p = 0; p < 8; p++)
            split2(tile[(ko + 2 * p) * 65 + n], tile[(ko + 2 * p + 1) * 65 + n],
                   hi[p], lo[p]);
        size_t dst = (size_t)(n0 + n) * F_ + k0 + ko;
        *reinterpret_cast<uint4*>(g_wh + dst)     = make_uint4(hi[0], hi[1], hi[2], hi[3]);
        *reinterpret_cast<uint4*>(g_wh + dst + 8) = make_uint4(hi[4], hi[5], hi[6], hi[7]);
        *reinterpret_cast<uint4*>(g_wl + dst)     = make_uint4(lo[0], lo[1], lo[2], lo[3]);
        *reinterpret_cast<uint4*>(g_wl + dst + 8) = make_uint4(lo[4], lo[5], lo[6], lo[7]);
    }
}

// ---------------------------------------------------------------------------
// Kernel 1: mma.sync GEMM, 3-pass hi/lo, fragments via ldmatrix.x4.
// CTA tile 128x64, BK=32, grid (32,4), 256 threads = 8 warps (2m x 4n),
// warp tile m64 x n16. Double-buffered smem, one __syncthreads per k-tile.
// (R8 configuration — best measured.)
// ---------------------------------------------------------------------------
#define AH_E  0
#define AL_E  (128 * PADK)
#define BH_E  (2 * 128 * PADK)
#define BL_E  (2 * 128 * PADK + 64 * PADK)
#define BUFE  (2 * 128 * PADK + 2 * 64 * PADK)      // 15360 bf16 = 30720 B
#define GEMM_SMEM (2 * BUFE * 2)                    // 61440 B

__global__ __launch_bounds__(256, 1)
void gate_gemm_mma(const float* __restrict__ bl) {
    extern __shared__ __nv_bfloat16 sm[];

    const int tid  = threadIdx.x;
    const int warp = tid >> 5;
    const int lane = tid & 31;
    const int wm   = (warp >> 2) * 64;      // 0 or 64
    const int wn   = (warp & 3) * 16;       // 0,16,32,48
    const int g    = lane >> 2;
    const int tq   = lane & 3;
    const int m0   = blockIdx.x * 128;
    const int n0   = blockIdx.y * 64;

    // ldmatrix per-lane source rows (element offsets into a buffer)
    const int arow = wm + (lane & 15);
    const int akh  = ((lane >> 4) & 1) * 8;               // A k-half
    const int brow = wn + (lane & 7) + ((lane >> 4) & 1) * 8;
    const int bkh  = ((lane >> 3) & 1) * 8;               // B k-half
    const uint32_t sb = smaddr(sm);
    const uint32_t aAh = sb + 2 * (AH_E + arow * PADK + akh);
    const uint32_t aAl = sb + 2 * (AL_E + arow * PADK + akh);
    const uint32_t aBh = sb + 2 * (BH_E + brow * PADK + bkh);
    const uint32_t aBl = sb + 2 * (BL_E + brow * PADK + bkh);

    // staging maps (LDG.128 -> STS.128 of pre-split data)
    const int srow = tid >> 2;              // 0..63
    const int sv   = tid & 3;               // 16B vec within 64B
    const uint4* pxh0 = reinterpret_cast<const uint4*>(g_xh + (size_t)(m0 + srow) * F_) + sv;
    const uint4* pxh1 = reinterpret_cast<const uint4*>(g_xh + (size_t)(m0 + 64 + srow) * F_) + sv;
    const uint4* pxl0 = reinterpret_cast<const uint4*>(g_xl + (size_t)(m0 + srow) * F_) + sv;
    const uint4* pxl1 = reinterpret_cast<const uint4*>(g_xl + (size_t)(m0 + 64 + srow) * F_) + sv;
    const uint4* pwh  = reinterpret_cast<const uint4*>(g_wh + (size_t)(n0 + srow) * F_) + sv;
    const uint4* pwl  = reinterpret_cast<const uint4*>(g_wl + (size_t)(n0 + srow) * F_) + sv;

    float acc[4][2][4];
#pragma unroll
    for (int mt = 0; mt < 4; mt++)
#pragma unroll
        for (int nt = 0; nt < 2; nt++)
#pragma unroll
            for (int r = 0; r < 4; r++) acc[mt][nt][r] = 0.f;

    uint4 rh0 = pxh0[0], rh1 = pxh1[0], rl0 = pxl0[0], rl1 = pxl1[0];
    uint4 rbh = pwh[0],  rbl = pwl[0];

    const int NKT = F_ / 32;
    for (int kt = 0; kt < NKT; kt++) {
        const int be = (kt & 1) * BUFE;
        __nv_bfloat16* buf = sm + be;
        *reinterpret_cast<uint4*>(buf + AH_E + (size_t)srow * PADK + sv * 8)        = rh0;
        *reinterpret_cast<uint4*>(buf + AH_E + (size_t)(64 + srow) * PADK + sv * 8) = rh1;
        *reinterpret_cast<uint4*>(buf + AL_E + (size_t)srow * PADK + sv * 8)        = rl0;
        *reinterpret_cast<uint4*>(buf + AL_E + (size_t)(64 + srow) * PADK + sv * 8) = rl1;
        *reinterpret_cast<uint4*>(buf + BH_E + (size_t)srow * PADK + sv * 8)        = rbh;
        *reinterpret_cast<uint4*>(buf + BL_E + (size_t)srow * PADK + sv * 8)        = rbl;
        __syncthreads();

        if (kt < NKT - 1) {                 // prefetch next k-tile
            int o = (kt + 1) * 4;
            rh0 = pxh0[o]; rh1 = pxh1[o]; rl0 = pxl0[o]; rl1 = pxl1[o];
            rbh = pwh[o];  rbl = pwl[o];
        }

        const uint32_t bofs = 2 * be;
#pragma unroll
        for (int ks = 0; ks < 32; ks += 16) {
            uint32_t bh[4], blo[4];
            ldsm4(bh,  aBh + bofs + 2 * ks);
            ldsm4(blo, aBl + bofs + 2 * ks);
#pragma unroll
            for (int mt = 0; mt < 4; mt++) {
                uint32_t ah[4], al[4];
                ldsm4(ah, aAh + bofs + 2 * (mt * 16 * PADK + ks));
                ldsm4(al, aAl + bofs + 2 * (mt * 16 * PADK + ks));
                mma_bf16(acc[mt][0], ah, bh[0],  bh[1]);
                mma_bf16(acc[mt][1], ah, bh[2],  bh[3]);
                mma_bf16(acc[mt][0], al, bh[0],  bh[1]);
                mma_bf16(acc[mt][1], al, bh[2],  bh[3]);
                mma_bf16(acc[mt][0], ah, blo[0], blo[1]);
                mma_bf16(acc[mt][1], ah, blo[2], blo[3]);
            }
        }
        // single barrier per iter is safe with double buffering (see R7 note)
    }

    // epilogue: bias + store (c0,c1 at row g, c2,c3 at g+8)
#pragma unroll
    for (int nt = 0; nt < 2; nt++) {
        int n = n0 + wn + nt * 8 + 2 * tq;
        float2 bias = *reinterpret_cast<const float2*>(&bl[n]);
#pragma unroll
        for (int mt = 0; mt < 4; mt++) {
            int m = m0 + wm + mt * 16 + g;
            float2 o0, o1;
            o0.x = acc[mt][nt][0] + bias.x;  o0.y = acc[mt][nt][1] + bias.y;
            o1.x = acc[mt][nt][2] + bias.x;  o1.y = acc[mt][nt][3] + bias.y;
            *reinterpret_cast<float2*>(&g_G[(size_t)m * G4 + n])       = o0;
            *reinterpret_cast<float2*>(&g_G[(size_t)(m + 8) * G4 + n]) = o1;
        }
    }
}

// ---------------------------------------------------------------------------
// Kernel 2: LSTM recurrence. 1 CTA/batch, 256 threads = 8 warps.
// Lane l of warp w: dot for (gate = l>>3, unit = 8w + (l&7)); G in smem.
// Issue-count-tuned step: 16x LDS.128 for h, 32 FFMA2, f32x2 add tree,
// ex2.approx + rcp.approx activations (no div.rn sequences), own-gate
// activation then shuffle. One __syncthreads per step.
// ---------------------------------------------------------------------------
__device__ __forceinline__ unsigned long long pk2(float lo, float hi) {
    unsigned long long r;
    asm("mov.b64 %0, {%1, %2};" : "=l"(r) : "f"(lo), "f"(hi));
    return r;
}
__device__ __forceinline__ unsigned long long fma2_(unsigned long long a,
                                                    unsigned long long b,
                                                    unsigned long long c) {
    unsigned long long d;
    asm("fma.rn.f32x2 %0, %1, %2, %3;" : "=l"(d) : "l"(a), "l"(b), "l"(c));
    return d;
}
__device__ __forceinline__ unsigned long long add2_(unsigned long long a,
                                                    unsigned long long b) {
    unsigned long long d;
    asm("add.rn.f32x2 %0, %1, %2;" : "=l"(d) : "l"(a), "l"(b));
    return d;
}
__device__ __forceinline__ void upk2(float& lo, float& hi, unsigned long long v) {
    asm("mov.b64 {%0, %1}, %2;" : "=f"(lo), "=f"(hi) : "l"(v));
}
__device__ __forceinline__ float ex2_(float v) {
    float r; asm("ex2.approx.f32 %0, %1;" : "=f"(r) : "f"(v)); return r;
}
__device__ __forceinline__ float rcp_(float v) {
    float r; asm("rcp.approx.f32 %0, %1;" : "=f"(r) : "f"(v)); return r;
}

__global__ __launch_bounds__(256, 1)
void lstm_rec(const float* __restrict__ Wh, float* __restrict__ out) {
    const int b   = blockIdx.x;
    const int tid = threadIdx.x;
    const int w   = tid >> 5;
    const int l   = tid & 31;
    const int u   = 8 * w + (l & 7);
    const int gq  = l >> 3;
    const int n   = gq * 64 + u;

    __shared__ __align__(16) float Gsh[W_ * G4];     // 32 KB
    __shared__ __align__(16) float hbuf[2][H_];

    // activation act = fb * (1 / (1 + 2^{fa2*v})) + fc  (tanh for gate 2)
    const float L2E = 1.4426950408889634f;
    const float fa2 = (gq == 2) ? -2.0f * L2E : -1.0f * L2E;
    const float fb  = (gq == 2) ?  2.0f :  1.0f;
    const float fc  = (gq == 2) ? -1.0f :  0.0f;

    unsigned long long wh2[32];
#pragma unroll
    for (int kk = 0; kk < 32; kk++)
        wh2[kk] = pk2(Wh[(2 * kk) * G4 + n], Wh[(2 * kk + 1) * G4 + n]);

    {   // stage this batch's G slice into smem (coalesced)
        const float4* src = reinterpret_cast<const float4*>(g_G + (size_t)b * W_ * G4);
        float4* dst = reinterpret_cast<float4*>(Gsh);
#pragma unroll
        for (int j = 0; j < 8; j++) dst[j * 256 + tid] = src[j * 256 + tid];
    }
    if (tid < H_) hbuf[0][tid] = 0.0f;
    float c = 0.0f;
    __syncthreads();

    int p = 0;
    for (int t = 0; t < W_; t++) {
        const ulonglong2* h4 = reinterpret_cast<const ulonglong2*>(hbuf[p]);

        unsigned long long a0 = pk2(Gsh[t * G4 + n], 0.0f);
        unsigned long long a1 = 0ull, a2 = 0ull, a3 = 0ull;
#pragma unroll
        for (int kk = 0; kk < 8; kk++) {          // 16 LDS.128, 32 FFMA2
            ulonglong2 qa = h4[kk];
            ulonglong2 qb = h4[kk + 8];
            a0 = fma2_(qa.x, wh2[2 * kk],      a0);
            a1 = fma2_(qa.y, wh2[2 * kk + 1],  a1);
            a2 = fma2_(qb.x, wh2[16 + 2 * kk], a2);
            a3 = fma2_(qb.y, wh2[17 + 2 * kk], a3);
        }
        unsigned long long s = add2_(add2_(a0, a1), add2_(a2, a3));
        float slo, shi;
        upk2(slo, shi, s);
        float v = slo + shi;

        // own-gate activation: 1 ex2 + 1 rcp (MUFU), fully saturating
        float act = fmaf(fb, rcp_(1.0f + ex2_(fa2 * v)), fc);

        // gather activated gates for unit (l&7) from lanes {0,8,16,24}+(l&7)
        int src = l & 7;
        float ig = __shfl_sync(0xFFFFFFFFu, act, src);
        float fg = __shfl_sync(0xFFFFFFFFu, act, src + 8);
        float gg = __shfl_sync(0xFFFFFFFFu, act, src + 16);
        float og = __shfl_sync(0xFFFFFFFFu, act, src + 24);

        c = fg * c + ig * gg;
        // tanh(c) = 2 / (1 + 2^{-2*log2e*c}) - 1
        float tc = fmaf(2.0f, rcp_(1.0f + ex2_(-2.0f * L2E * c)), -1.0f);
        float hn = og * tc;
        if (l < 8) {
            out[(size_t)b * (W_ * H_) + t * H_ + u] = c;   // output = cell state
            hbuf[p ^ 1][u] = hn;
        }
        p ^= 1;
        __syncthreads();
    }
}

// ---------------------------------------------------------------------------
// Launch
// ---------------------------------------------------------------------------
extern "C" void kernel_launch(void* const* d_in, const int* in_sizes, int n_in,
                              void* d_out, int out_size) {
    const float* x   = (const float*)d_in[0];   // [B, F, W]
    // d_in[1..5] (attention params) are dead: softmax over size-1 axis == 1.
    const float* Wx  = (const float*)d_in[6];   // [F, 4H]
    const float* Wh  = (const float*)d_in[7];   // [H, 4H]
    const float* blm = (const float*)d_in[8];   // [4H]
    float* out = (float*)d_out;                 // [B, W, H]

    cudaFuncSetAttribute(gate_gemm_mma,
                         cudaFuncAttributeMaxDynamicSharedMemorySize, GEMM_SMEM);

    split_xw<<<1088, 256>>>(x, Wx);
    gate_gemm_mma<<<dim3(32, 4), 256, GEMM_SMEM>>>(blm);
    lstm_rec<<<B_, 256>>>(Wh, out);
}

// round 11
// speedup vs baseline: 1.6684x; 1.6684x over previous
#include <cuda_runtime.h>
#include <cuda_bf16.h>
#include <cstdint>

// ---------------------------------------------------------------------------
// Problem: B=128, F=1024, W=32, H=64.  softmax over a size-1 axis == 1, so the
// attention branch is dead; model = plain LSTM, output = CELL state per step.
//   G[m][n] = sum_k x[b][k][t] * Wx[k][n] + b_lstm[n],  m = b*32 + t
// GEMM: bf16 mma.sync, 3-pass hi/lo compensation (rel_err ~1.6e-5 proven).
// x split stored [k][m] so the split needs NO transpose (m=b*32+t is already
// contiguous in x's t axis); GEMM A-fragments come via ldmatrix.trans.
// ---------------------------------------------------------------------------
#define B_   128
#define F_   1024
#define W_   32
#define H_   64
#define G4   256
#define M_   4096                // B_*W_
#define PADK 40                  // B smem row stride (bf16)
#define PADM 136                 // A smem row stride (bf16): 272B, ldsm-safe

__device__ float          g_G [M_ * G4];         // gate preactivations, 4 MB
__device__ __nv_bfloat16  g_xh[F_ * M_];         // x hi  [k][m], 8 MB
__device__ __nv_bfloat16  g_xl[F_ * M_];         // x lo  [k][m]
__device__ __nv_bfloat16  g_wh[G4 * F_];         // Wx^T hi [n][k], 512 KB
__device__ __nv_bfloat16  g_wl[G4 * F_];         // Wx^T lo

// ---- helpers ---------------------------------------------------------------
__device__ __forceinline__ uint32_t smaddr(const void* p) {
    return (uint32_t)__cvta_generic_to_shared(p);
}
__device__ __forceinline__ void split2(float a, float b, uint32_t& hi, uint32_t& lo) {
    uint32_t ua = __float_as_uint(a), ub = __float_as_uint(b);
    hi = (ua >> 16) | (ub & 0xFFFF0000u);                   // truncated bf16 pair
    float la = a - __uint_as_float(ua & 0xFFFF0000u);
    float lb = b - __uint_as_float(ub & 0xFFFF0000u);
    __nv_bfloat162 p = __floats2bfloat162_rn(la, lb);
    lo = *reinterpret_cast<uint32_t*>(&p);
}
__device__ __forceinline__ void mma_bf16(float* c,
                                         const uint32_t* a, uint32_t b0, uint32_t b1) {
    asm volatile(
        "mma.sync.aligned.m16n8k16.row.col.f32.bf16.bf16.f32 "
        "{%0,%1,%2,%3}, {%4,%5,%6,%7}, {%8,%9}, {%0,%1,%2,%3};\n"
        : "+f"(c[0]), "+f"(c[1]), "+f"(c[2]), "+f"(c[3])
        : "r"(a[0]), "r"(a[1]), "r"(a[2]), "r"(a[3]), "r"(b0), "r"(b1));
}
__device__ __forceinline__ void ldsm4(uint32_t* r, uint32_t addr) {
    asm volatile("ldmatrix.sync.aligned.m8n8.x4.shared.b16 {%0,%1,%2,%3}, [%4];"
                 : "=r"(r[0]), "=r"(r[1]), "=r"(r[2]), "=r"(r[3]) : "r"(addr));
}
__device__ __forceinline__ void ldsm4t(uint32_t* r, uint32_t addr) {
    asm volatile("ldmatrix.sync.aligned.m8n8.x4.trans.shared.b16 {%0,%1,%2,%3}, [%4];"
                 : "=r"(r[0]), "=r"(r[1]), "=r"(r[2]), "=r"(r[3]) : "r"(addr));
}

// ---------------------------------------------------------------------------
// Kernel 0 (fused): hi/lo split.
//   blocks [0, 1024):    x [B][F][W] -> g_xh/g_xl [k=f][m=b*32+t]  (NO transpose:
//                        pure LDG.128 -> STG, fully coalesced)
//   blocks [1024, 1088): Wx [K][N]   -> g_wh/g_wl [n][k]  (small; smem transpose)
// ---------------------------------------------------------------------------
__global__ __launch_bounds__(256) void split_xw(const float* __restrict__ x,
                                                const float* __restrict__ Wx) {
    const int tid = threadIdx.x;
    const int bid = blockIdx.x;

    if (bid < 1024) {
        const int gtid = bid * 256 + tid;
#pragma unroll
        for (int j = 0; j < 4; j++) {
            int idx = j * 262144 + gtid;        // over (f, b, tq)
            int tq  = idx & 7;
            int rem = idx >> 3;
            int b   = rem & 127;
            int f   = rem >> 7;                 // 0..1023
            float4 v = *reinterpret_cast<const float4*>(
                x + ((size_t)b * F_ + f) * W_ + tq * 4);
            uint32_t h0, l0, h1, l1;
            split2(v.x, v.y, h0, l0);
            split2(v.z, v.w, h1, l1);
            size_t dst = (size_t)f * M_ + b * 32 + tq * 4;
            *reinterpret_cast<uint2*>(g_xh + dst) = make_uint2(h0, h1);
            *reinterpret_cast<uint2*>(g_xl + dst) = make_uint2(l0, l1);
        }
    } else {
        __shared__ float tile[64 * 65];
        const int id = bid - 1024;
        const int k0 = (id & 15) * 64;
        const int n0 = (id >> 4) * 64;
#pragma unroll
        for (int i = 0; i < 4; i++) {
            int idx = i * 256 + tid;
            int k = idx >> 4, nq = idx & 15;
            float4 v = *reinterpret_cast<const float4*>(
                Wx + (size_t)(k0 + k) * G4 + n0 + nq * 4);
            tile[k * 65 + nq * 4 + 0] = v.x; tile[k * 65 + nq * 4 + 1] = v.y;
            tile[k * 65 + nq * 4 + 2] = v.z; tile[k * 65 + nq * 4 + 3] = v.w;
        }
        __syncthreads();
        const int n  = tid >> 2;
        const int ko = (tid & 3) * 16;
        uint32_t hi[8], lo[8];
#pragma unroll
        for (int p = 0; p < 8; p++)
            split2(tile[(ko + 2 * p) * 65 + n], tile[(ko + 2 * p + 1) * 65 + n],
                   hi[p], lo[p]);
        size_t dst = (size_t)(n0 + n) * F_ + k0 + ko;
        *reinterpret_cast<uint4*>(g_wh + dst)     = make_uint4(hi[0], hi[1], hi[2], hi[3]);
        *reinterpret_cast<uint4*>(g_wh + dst + 8) = make_uint4(hi[4], hi[5], hi[6], hi[7]);
        *reinterpret_cast<uint4*>(g_wl + dst)     = make_uint4(lo[0], lo[1], lo[2], lo[3]);
        *reinterpret_cast<uint4*>(g_wl + dst + 8) = make_uint4(lo[4], lo[5], lo[6], lo[7]);
    }
}

// ---------------------------------------------------------------------------
// Kernel 1: mma.sync GEMM, 3-pass hi/lo. A tiles stored [k=32][m=128] (PADM),
// A-fragments via ldmatrix.x4.trans; B tiles [n=64][k=32] (PADK), non-trans.
// CTA tile 128x64, BK=32, grid (32,4), 256 threads = 8 warps (2m x 4n),
// warp tile m64 x n16. Double-buffered smem, one __syncthreads per k-tile.
// ---------------------------------------------------------------------------
#define AH_E  0
#define AL_E  (32 * PADM)                            // 4352
#define BH_E  (2 * 32 * PADM)                        // 8704
#define BL_E  (2 * 32 * PADM + 64 * PADK)            // 11264
#define BUFE  (2 * 32 * PADM + 2 * 64 * PADK)        // 13824 elems = 27648 B
#define GEMM_SMEM (2 * BUFE * 2)                     // 55296 B

__global__ __launch_bounds__(256, 1)
void gate_gemm_mma(const float* __restrict__ bl) {
    extern __shared__ __nv_bfloat16 sm[];

    const int tid  = threadIdx.x;
    const int warp = tid >> 5;
    const int lane = tid & 31;
    const int wm   = (warp >> 2) * 64;      // 0 or 64
    const int wn   = (warp & 3) * 16;       // 0,16,32,48
    const int g    = lane >> 2;
    const int tq   = lane & 3;
    const int m0   = blockIdx.x * 128;
    const int n0   = blockIdx.y * 64;

    const uint32_t sb = smaddr(sm);
    // A trans-ldmatrix per-lane offsets: krow = ks + (lane&7) + ((lane>>4)&1)*8,
    // mcol = wm + mt*16 + ((lane>>3)&1)*8.
    const int aoff = ((lane & 7) + ((lane >> 4) & 1) * 8) * PADM
                   + ((lane >> 3) & 1) * 8 + wm;
    const uint32_t aAh = sb + 2 * (AH_E + aoff);
    const uint32_t aAl = sb + 2 * (AL_E + aoff);
    // B non-trans (unchanged layout, proven)
    const int brow = wn + (lane & 7) + ((lane >> 4) & 1) * 8;
    const int bkh  = ((lane >> 3) & 1) * 8;
    const uint32_t aBh = sb + 2 * (BH_E + brow * PADK + bkh);
    const uint32_t aBl = sb + 2 * (BL_E + brow * PADK + bkh);

    // staging maps
    //   A: [32 k][128 m]: 32 rows x 16 uint4; 8 threads/row, 2 uint4/thread
    const int arow = tid >> 3;              // 0..31
    const int amc  = (tid & 7) * 16;        // element col (2 x uint4: amc, amc+8)
    const __nv_bfloat16* axh = g_xh + (size_t)arow * M_ + m0 + amc;
    const __nv_bfloat16* axl = g_xl + (size_t)arow * M_ + m0 + amc;
    //   B: [64 n][32 k]: 64 rows x 4 uint4; 4 threads/row, 1 uint4/thread
    const int srow = tid >> 2;              // 0..63
    const int sv   = tid & 3;
    const uint4* pwh = reinterpret_cast<const uint4*>(g_wh + (size_t)(n0 + srow) * F_) + sv;
    const uint4* pwl = reinterpret_cast<const uint4*>(g_wl + (size_t)(n0 + srow) * F_) + sv;

    float acc[4][2][4];
#pragma unroll
    for (int mt = 0; mt < 4; mt++)
#pragma unroll
        for (int nt = 0; nt < 2; nt++)
#pragma unroll
            for (int r = 0; r < 4; r++) acc[mt][nt][r] = 0.f;

    uint4 rah0 = *reinterpret_cast<const uint4*>(axh);
    uint4 rah1 = *reinterpret_cast<const uint4*>(axh + 8);
    uint4 ral0 = *reinterpret_cast<const uint4*>(axl);
    uint4 ral1 = *reinterpret_cast<const uint4*>(axl + 8);
    uint4 rbh  = pwh[0];
    uint4 rbl  = pwl[0];

    const int NKT = F_ / 32;
    for (int kt = 0; kt < NKT; kt++) {
        const int be = (kt & 1) * BUFE;
        __nv_bfloat16* buf = sm + be;
        *reinterpret_cast<uint4*>(buf + AH_E + arow * PADM + amc)     = rah0;
        *reinterpret_cast<uint4*>(buf + AH_E + arow * PADM + amc + 8) = rah1;
        *reinterpret_cast<uint4*>(buf + AL_E + arow * PADM + amc)     = ral0;
        *reinterpret_cast<uint4*>(buf + AL_E + arow * PADM + amc + 8) = ral1;
        *reinterpret_cast<uint4*>(buf + BH_E + srow * PADK + sv * 8)  = rbh;
        *reinterpret_cast<uint4*>(buf + BL_E + srow * PADK + sv * 8)  = rbl;
        __syncthreads();

        if (kt < NKT - 1) {                 // prefetch next k-tile
            const size_t ao = (size_t)(kt + 1) * 32 * M_;
            rah0 = *reinterpret_cast<const uint4*>(axh + ao);
            rah1 = *reinterpret_cast<const uint4*>(axh + ao + 8);
            ral0 = *reinterpret_cast<const uint4*>(axl + ao);
            ral1 = *reinterpret_cast<const uint4*>(axl + ao + 8);
            rbh  = pwh[(kt + 1) * 4];
            rbl  = pwl[(kt + 1) * 4];
        }

        const uint32_t bofs = 2 * be;
#pragma unroll
        for (int ks = 0; ks < 32; ks += 16) {
            uint32_t bh[4], blo[4];
            ldsm4(bh,  aBh + bofs + 2 * ks);
            ldsm4(blo, aBl + bofs + 2 * ks);
#pragma unroll
            for (int mt = 0; mt < 4; mt++) {
                const uint32_t ao = bofs + 2 * (ks * PADM + mt * 16);
                uint32_t ah[4], al[4];
                ldsm4t(ah, aAh + ao);
                ldsm4t(al, aAl + ao);
                mma_bf16(acc[mt][0], ah, bh[0],  bh[1]);
                mma_bf16(acc[mt][1], ah, bh[2],  bh[3]);
                mma_bf16(acc[mt][0], al, bh[0],  bh[1]);
                mma_bf16(acc[mt][1], al, bh[2],  bh[3]);
                mma_bf16(acc[mt][0], ah, blo[0], blo[1]);
                mma_bf16(acc[mt][1], ah, blo[2], blo[3]);
            }
        }
        // single barrier per iter is safe with double buffering (see R7 note)
    }

    // epilogue: bias + store (c0,c1 at row g, c2,c3 at g+8)
#pragma unroll
    for (int nt = 0; nt < 2; nt++) {
        int n = n0 + wn + nt * 8 + 2 * tq;
        float2 bias = *reinterpret_cast<const float2*>(&bl[n]);
#pragma unroll
        for (int mt = 0; mt < 4; mt++) {
            int m = m0 + wm + mt * 16 + g;
            float2 o0, o1;
            o0.x = acc[mt][nt][0] + bias.x;  o0.y = acc[mt][nt][1] + bias.y;
            o1.x = acc[mt][nt][2] + bias.x;  o1.y = acc[mt][nt][3] + bias.y;
            *reinterpret_cast<float2*>(&g_G[(size_t)m * G4 + n])       = o0;
            *reinterpret_cast<float2*>(&g_G[(size_t)(m + 8) * G4 + n]) = o1;
        }
    }
}

// ---------------------------------------------------------------------------
// Kernel 2: LSTM recurrence — R8 structure (proven 18.4us) with two deltas:
// rcp.approx/ex2.approx instead of div.rn sequences, and unroll 1 on the
// t loop (full unroll blows I$ at grid=128 and spills wh2).
// ---------------------------------------------------------------------------
__device__ __forceinline__ unsigned long long pk2(float lo, float hi) {
    unsigned long long r;
    asm("mov.b64 %0, {%1, %2};" : "=l"(r) : "f"(lo), "f"(hi));
    return r;
}
__device__ __forceinline__ unsigned long long fma2_(unsigned long long a,
                                                    unsigned long long b,
                                                    unsigned long long c) {
    unsigned long long d;
    asm("fma.rn.f32x2 %0, %1, %2, %3;" : "=l"(d) : "l"(a), "l"(b), "l"(c));
    return d;
}
__device__ __forceinline__ void upk2(float& lo, float& hi, unsigned long long v) {
    asm("mov.b64 {%0, %1}, %2;" : "=f"(lo), "=f"(hi) : "l"(v));
}
__device__ __forceinline__ float ex2_(float v) {
    float r; asm("ex2.approx.f32 %0, %1;" : "=f"(r) : "f"(v)); return r;
}
__device__ __forceinline__ float rcp_(float v) {
    float r; asm("rcp.approx.f32 %0, %1;" : "=f"(r) : "f"(v)); return r;
}

__global__ __launch_bounds__(256, 1)
void lstm_rec(const float* __restrict__ Wh, float* __restrict__ out) {
    const int b   = blockIdx.x;
    const int tid = threadIdx.x;
    const int w   = tid >> 5;
    const int l   = tid & 31;
    const int u   = 8 * w + (l & 7);
    const int gq  = l >> 3;
    const int n   = gq * 64 + u;

    __shared__ __align__(16) float Gsh[W_ * G4];     // 32 KB
    __shared__ __align__(16) float hbuf[2][H_];

    // act = fb * (1 / (1 + 2^{fa2*v})) + fc  (tanh for gate 2, sigmoid else)
    const float L2E = 1.4426950408889634f;
    const float fa2 = (gq == 2) ? -2.0f * L2E : -L2E;
    const float fb  = (gq == 2) ?  2.0f :  1.0f;
    const float fc  = (gq == 2) ? -1.0f :  0.0f;

    unsigned long long wh2[32];
#pragma unroll
    for (int kk = 0; kk < 32; kk++)
        wh2[kk] = pk2(Wh[(2 * kk) * G4 + n], Wh[(2 * kk + 1) * G4 + n]);

    {   // stage this batch's G slice into smem (coalesced)
        const float4* src = reinterpret_cast<const float4*>(g_G + (size_t)b * W_ * G4);
        float4* dst = reinterpret_cast<float4*>(Gsh);
#pragma unroll
        for (int j = 0; j < 8; j++) dst[j * 256 + tid] = src[j * 256 + tid];
    }
    if (tid < H_) hbuf[0][tid] = 0.0f;
    float c = 0.0f;
    __syncthreads();

    int p = 0;
#pragma unroll 1
    for (int t = 0; t < W_; t++) {
        const unsigned long long* h2 =
            reinterpret_cast<const unsigned long long*>(hbuf[p]);

        unsigned long long a0 = pk2(Gsh[t * G4 + n], 0.0f);
        unsigned long long a1 = 0ull, a2 = 0ull, a3 = 0ull;
#pragma unroll
        for (int kk = 0; kk < 8; kk++) {
            a0 = fma2_(h2[kk],      wh2[kk],      a0);
            a1 = fma2_(h2[8 + kk],  wh2[8 + kk],  a1);
            a2 = fma2_(h2[16 + kk], wh2[16 + kk], a2);
            a3 = fma2_(h2[24 + kk], wh2[24 + kk], a3);
        }
        float s0, s1, s2, s3, s4, s5, s6, s7;
        upk2(s0, s1, a0); upk2(s2, s3, a1);
        upk2(s4, s5, a2); upk2(s6, s7, a3);
        float v = ((s0 + s1) + (s2 + s3)) + ((s4 + s5) + (s6 + s7));

        // own-gate activation: 1 ex2 + 1 rcp (MUFU only, no div.rn)
        float act = fmaf(fb, rcp_(1.0f + ex2_(fa2 * v)), fc);

        int src = l & 7;
        float ig = __shfl_sync(0xFFFFFFFFu, act, src);
        float fg = __shfl_sync(0xFFFFFFFFu, act, src + 8);
        float gg = __shfl_sync(0xFFFFFFFFu, act, src + 16);
        float og = __shfl_sync(0xFFFFFFFFu, act, src + 24);

        c = fg * c + ig * gg;
        float tc = fmaf(2.0f, rcp_(1.0f + ex2_(-2.0f * L2E * c)), -1.0f);  // tanh(c)
        float hn = og * tc;
        if (l < 8) {
            out[(size_t)b * (W_ * H_) + t * H_ + u] = c;   // output = cell state
            hbuf[p ^ 1][u] = hn;
        }
        p ^= 1;
        __syncthreads();
    }
}

// ---------------------------------------------------------------------------
// Launch
// ---------------------------------------------------------------------------
extern "C" void kernel_launch(void* const* d_in, const int* in_sizes, int n_in,
                              void* d_out, int out_size) {
    const float* x   = (const float*)d_in[0];   // [B, F, W]
    // d_in[1..5] (attention params) are dead: softmax over size-1 axis == 1.
    const float* Wx  = (const float*)d_in[6];   // [F, 4H]
    const float* Wh  = (const float*)d_in[7];   // [H, 4H]
    const float* blm = (const float*)d_in[8];   // [4H]
    float* out = (float*)d_out;                 // [B, W, H]

    cudaFuncSetAttribute(gate_gemm_mma,
                         cudaFuncAttributeMaxDynamicSharedMemorySize, GEMM_SMEM);

    split_xw<<<1088, 256>>>(x, Wx);
    gate_gemm_mma<<<dim3(32, 4), 256, GEMM_SMEM>>>(blm);
    lstm_rec<<<B_, 256>>>(Wh, out);
}